// round 12
// baseline (speedup 1.0000x reference)
#include <cuda_runtime.h>
#include <cuda_fp16.h>
#include <math.h>
#include <stdint.h>

// ---------------- problem constants ----------------
#define SEQ    2048
#define NBATCH 2
#define TOK    (SEQ*NBATCH)
#define DIM    2048
#define QL     1536
#define KVL    512
#define NH     16
#define NOPE   128
#define ROPE_D 64
#define QKH    (NOPE+ROPE_D)
#define VH     128
#define KD     (KVL+ROPE_D)       // 576
#define SCALE_F 0.07216878364870322f
#define EPS_F  1e-6f

// ---------------- fp32 scratch ----------------
static __device__ __align__(16) float g_qa  [(size_t)TOK*QL];
static __device__ __align__(16) float g_q   [(size_t)TOK*NH*QKH];
static __device__ __align__(16) float g_kv  [(size_t)TOK*KD];

// ---------------- fp16 scratch ----------------
// activations: hi/lo split
static __device__ __align__(16) __half g_xh  [(size_t)TOK*DIM];
static __device__ __align__(16) __half g_xl  [(size_t)TOK*DIM];
static __device__ __align__(16) __half g_qah [(size_t)TOK*QL];
static __device__ __align__(16) __half g_qal [(size_t)TOK*QL];
static __device__ __align__(16) __half g_qh  [(size_t)TOK*NH*QKH];
static __device__ __align__(16) __half g_ql  [(size_t)TOK*NH*QKH];
static __device__ __align__(16) __half g_oah [(size_t)TOK*NH*KVL];
static __device__ __align__(16) __half g_oal [(size_t)TOK*NH*KVL];
static __device__ __align__(16) __half g_o2h [(size_t)TOK*NH*VH];
static __device__ __align__(16) __half g_o2l [(size_t)TOK*NH*VH];
// weights: single fp16
static __device__ __align__(16) __half g_wqa16 [(size_t)QL*DIM];
static __device__ __align__(16) __half g_wqb16 [(size_t)NH*QKH*QL];
static __device__ __align__(16) __half g_wkva16[(size_t)KD*DIM];
static __device__ __align__(16) __half g_wkvb16[(size_t)NH*(NOPE+VH)*KVL];
static __device__ __align__(16) __half g_wkvbt16[(size_t)NH*KVL*NOPE];
static __device__ __align__(16) __half g_wo16  [(size_t)DIM*NH*VH];
// flash-packed Q [t][h][576] and K [t][576], Q pre-scaled, hi/lo
static __device__ __align__(16) __half g_qfh [(size_t)TOK*NH*KD];
static __device__ __align__(16) __half g_qfl [(size_t)TOK*NH*KD];
static __device__ __align__(16) __half g_kfh [(size_t)TOK*KD];
static __device__ __align__(16) __half g_kfl [(size_t)TOK*KD];

// ======================= helpers =======================
__device__ __forceinline__ uint32_t smem_u32(const void* p) {
    uint32_t a;
    asm("{ .reg .u64 t; cvta.to.shared.u64 t, %1; cvt.u32.u64 %0, t; }" : "=r"(a) : "l"(p));
    return a;
}
__device__ __forceinline__ void cpa16(uint32_t dst, const void* src, bool ok) {
    int sz = ok ? 16 : 0;
    asm volatile("cp.async.cg.shared.global [%0], [%1], 16, %2;"
                 :: "r"(dst), "l"(src), "r"(sz) : "memory");
}
#define LDSM4(r, addr) \
    asm volatile("ldmatrix.sync.aligned.m8n8.x4.shared.b16 {%0,%1,%2,%3}, [%4];" \
        : "=r"((r)[0]), "=r"((r)[1]), "=r"((r)[2]), "=r"((r)[3]) : "r"(addr))
#define LDSM4T(r, addr) \
    asm volatile("ldmatrix.sync.aligned.m8n8.x4.trans.shared.b16 {%0,%1,%2,%3}, [%4];" \
        : "=r"((r)[0]), "=r"((r)[1]), "=r"((r)[2]), "=r"((r)[3]) : "r"(addr))
#define MMA16816(d, a, b0, b1) \
    asm volatile("mma.sync.aligned.m16n8k16.row.col.f32.f16.f16.f32 " \
        "{%0,%1,%2,%3},{%4,%5,%6,%7},{%8,%9},{%0,%1,%2,%3};" \
        : "+f"((d)[0]), "+f"((d)[1]), "+f"((d)[2]), "+f"((d)[3]) \
        : "r"((a)[0]), "r"((a)[1]), "r"((a)[2]), "r"((a)[3]), "r"(b0), "r"(b1))

__device__ __forceinline__ __half2 splith2(float a, float b, __half2& lo) {
    __half2 hi;
    hi.x = __float2half_rn(a); hi.y = __float2half_rn(b);
    lo.x = __float2half_rn(a - __half2float(hi.x));
    lo.y = __float2half_rn(b - __half2float(hi.y));
    return hi;
}

// ======================= 4-stage mma.sync fp16x2 GEMM, 2 CTAs/SM =======================
// C = Ah@Bh^T + Al@Bh^T.  A hi/lo fp16, B single fp16.
// 64B rows (4x16B granules), XOR swizzle: phys granule = g ^ ((row>>1)&3).
#define GROW(row, g) ((uint32_t)((row) * 64 + ((((g) ^ ((row) >> 1)) & 3) << 4)))
#define T_A    0
#define T_AL   8192
#define T_BH   16384
#define STG_SZ 24576
#define GSTAGES 4
#define GSM_TOTAL (GSTAGES*STG_SZ)   // 98304 -> 2 CTAs/SM

template<int OMODE>   // 0 = fp32 C; 2 = fp16 hi/lo scaled; 3 = both
__global__ __launch_bounds__(256, 2)
void gemm_mma(const __half* __restrict__ Ah, const __half* __restrict__ Al,
              int lda, long long aoffz,
              const __half* __restrict__ Bh,
              int ldb, long long boffz, int Nmax,
              float* __restrict__ C, int ldc, long long coffz,
              __half* __restrict__ Dh, __half* __restrict__ Dl,
              int ldd, long long doffz, float cscale,
              int K)
{
    extern __shared__ __align__(128) char sm[];
    const int tid = threadIdx.x;
    const int wid = tid >> 5, lane = tid & 31;
    const long long z = blockIdx.z;
    Ah += z * aoffz; Al += z * aoffz;
    Bh += z * boffz;
    const int m0 = blockIdx.y * 128;
    const int n0 = blockIdx.x * 128;
    const uint32_t sbase = smem_u32(sm);
    const int nch = K >> 5;

    float acc[4][4][4];
#pragma unroll
    for (int i = 0; i < 4; i++)
#pragma unroll
        for (int j = 0; j < 4; j++)
#pragma unroll
            for (int v = 0; v < 4; v++) acc[i][j][v] = 0.f;

    auto issue = [&](int c) {
        const int s = c % GSTAGES;
        const int k0 = c << 5;
        const uint32_t sb = sbase + s * STG_SZ;
#pragma unroll
        for (int i = 0; i < 2; i++) {
            int g = tid + i * 256;          // 0..511 granules per tile
            int row = g >> 2, cg = g & 3;
            uint32_t so = GROW(row, cg);
            size_t ao = (size_t)(m0 + row) * lda + k0 + cg * 8;
            cpa16(sb + T_A  + so, Ah + ao, true);
            cpa16(sb + T_AL + so, Al + ao, true);
            int nr = n0 + row;
            bool ok = nr < Nmax;
            int nrc = ok ? nr : (Nmax - 1);
            size_t bo = (size_t)nrc * ldb + k0 + cg * 8;
            cpa16(sb + T_BH + so, Bh + bo, ok);
        }
        asm volatile("cp.async.commit_group;" ::: "memory");
    };

#pragma unroll
    for (int i = 0; i < GSTAGES - 1; i++) if (i < nch) issue(i);

    const int my = wid >> 2;
    const int wx = wid & 3;

    for (int c = 0; c < nch; ++c) {
        int pend = nch - 1 - c;
        if (pend > GSTAGES - 2) pend = GSTAGES - 2;
        if (pend == 2)      asm volatile("cp.async.wait_group 2;" ::: "memory");
        else if (pend == 1) asm volatile("cp.async.wait_group 1;" ::: "memory");
        else                asm volatile("cp.async.wait_group 0;" ::: "memory");
        __syncthreads();
        if (c + GSTAGES - 1 < nch) issue(c + GSTAGES - 1);

        const uint32_t sb = sbase + (c % GSTAGES) * STG_SZ;
#pragma unroll
        for (int ks = 0; ks < 2; ks++) {
            const int kg = ks * 2;
            uint32_t bH[8];
#pragma unroll
            for (int np = 0; np < 2; np++) {
                int row = wx * 32 + np * 16 + (lane & 7) + ((lane >> 4) & 1) * 8;
                int g = kg + ((lane >> 3) & 1);
                uint32_t bd = sb + GROW(row, g);
                LDSM4(&bH[np * 4], bd + T_BH);
            }
#pragma unroll
            for (int mt = 0; mt < 4; mt++) {
                uint32_t aH[4], aL[4];
                int row = my * 64 + mt * 16 + (lane & 15);
                int g = kg + (lane >> 4);
                uint32_t ad = sb + GROW(row, g);
                LDSM4(aH, ad + T_A);
                LDSM4(aL, ad + T_AL);
#pragma unroll
                for (int nt = 0; nt < 4; nt++) {
                    MMA16816(acc[mt][nt], aH, bH[nt * 2], bH[nt * 2 + 1]);
                    MMA16816(acc[mt][nt], aL, bH[nt * 2], bH[nt * 2 + 1]);
                }
            }
        }
    }

    // ---- epilogue ----
#pragma unroll
    for (int mt = 0; mt < 4; mt++) {
        int row = m0 + my * 64 + mt * 16 + (lane >> 2);
#pragma unroll
        for (int nt = 0; nt < 4; nt++) {
            int col = n0 + wx * 32 + nt * 8 + (lane & 3) * 2;
            if (col < Nmax) {
                if (OMODE == 0 || OMODE == 3) {
                    float* cp = C + z * coffz;
                    *(float2*)(cp + (size_t)row * ldc + col) =
                        make_float2(acc[mt][nt][0], acc[mt][nt][1]);
                    *(float2*)(cp + (size_t)(row + 8) * ldc + col) =
                        make_float2(acc[mt][nt][2], acc[mt][nt][3]);
                }
                if (OMODE >= 2) {
                    __half* dh = Dh + z * doffz;
                    __half* dl = Dl + z * doffz;
                    __half2 lo0, lo1;
                    __half2 hi0 = splith2(acc[mt][nt][0] * cscale,
                                          acc[mt][nt][1] * cscale, lo0);
                    __half2 hi1 = splith2(acc[mt][nt][2] * cscale,
                                          acc[mt][nt][3] * cscale, lo1);
                    *(__half2*)(dh + (size_t)row * ldd + col)       = hi0;
                    *(__half2*)(dl + (size_t)row * ldd + col)       = lo0;
                    *(__half2*)(dh + (size_t)(row + 8) * ldd + col) = hi1;
                    *(__half2*)(dl + (size_t)(row + 8) * ldd + col) = lo1;
                }
            }
        }
    }
}

// ======================= flash attention =======================
// QK: 3-term fp16 (Qh·Kh + Qh·Kl + Ql·Kh).  PV: 2-term (Ph·Vh + Pl·Vh).
#define F_ROWB 1152
#define FQ_H   0
#define FQ_L   36864
#define FK_BUF 73728           // 2 x (hi 36864 + lo 36864)
#define FTAIL  221184
#define FSP0   FTAIL
#define FSP1   (FTAIL+4224)
#define FST_M  (FTAIL+8448)
#define FST_L  (FTAIL+8576)
#define FST_A  (FTAIL+8704)
#define FPH    FTAIL
#define FPL    (FTAIL+2560)
#define FLASH_SMEM 230912

__global__ __launch_bounds__(256, 1)
void flash_mma(const __half* __restrict__ Qh_g, const __half* __restrict__ Ql_g,
               const __half* __restrict__ Kh_g, const __half* __restrict__ Kl_g,
               __half* __restrict__ Oh, __half* __restrict__ Ol)
{
    extern __shared__ __align__(128) char sm[];
    const int tid = threadIdx.x, lane = tid & 31, wid = tid >> 5;
    const int q0 = blockIdx.x * 32, h = blockIdx.y, bb = blockIdx.z;
    const uint32_t sb = smem_u32(sm);
    float* m_s = (float*)(sm + FST_M);
    float* l_s = (float*)(sm + FST_L);
    float* a_s = (float*)(sm + FST_A);

    {
        size_t qbase = ((size_t)(bb * SEQ + q0)) * (NH * KD) + (size_t)h * KD;
        for (int i = tid; i < 4608; i += 256) {
            int hl = (i >= 2304);
            int j = hl ? i - 2304 : i;
            int row = j / 72, g = j - row * 72;
            uint32_t dst = sb + (hl ? FQ_L : FQ_H) + row * F_ROWB + ((g ^ (row & 7)) << 4);
            const __half* src = (hl ? Ql_g : Qh_g) + qbase + (size_t)row * (NH * KD) + g * 8;
            cpa16(dst, src, true);
        }
        asm volatile("cp.async.commit_group;" ::: "memory");
    }
    if (tid < 32) { m_s[tid] = -1e30f; l_s[tid] = 0.f; }

    auto load_k = [&](int kt, int s) {
        size_t kbase = ((size_t)bb * SEQ + kt * 32) * KD;
        uint32_t bufb = sb + FK_BUF + s * 73728;
        for (int i = tid; i < 4608; i += 256) {
            int hl = (i >= 2304);
            int j = hl ? i - 2304 : i;
            int row = j / 72, g = j - row * 72;
            uint32_t dst = bufb + hl * 36864 + row * F_ROWB + ((g ^ (row & 7)) << 4);
            const __half* src = (hl ? Kl_g : Kh_g) + kbase + (size_t)row * KD + g * 8;
            cpa16(dst, src, true);
        }
        asm volatile("cp.async.commit_group;" ::: "memory");
    };

    load_k(0, 0);

    const int nkt = (q0 >> 5) + 1;

    const int mw  = wid & 1;
    const int nw2 = (wid >> 1) & 1;
    const int kh  = wid >> 2;

    float oacc[2][8][4];
#pragma unroll
    for (int a = 0; a < 2; a++)
#pragma unroll
        for (int b = 0; b < 8; b++)
#pragma unroll
            for (int v = 0; v < 4; v++) oacc[a][b][v] = 0.f;

    for (int kt = 0; kt < nkt; kt++) {
        if (kt + 1 < nkt) {
            load_k(kt + 1, (kt + 1) & 1);
            asm volatile("cp.async.wait_group 1;" ::: "memory");
        } else {
            asm volatile("cp.async.wait_group 0;" ::: "memory");
        }
        __syncthreads();
        const uint32_t kb = sb + FK_BUF + (kt & 1) * 73728;

        float sa[2][4], sbv[2][4], sc[2][4];
#pragma unroll
        for (int nt = 0; nt < 2; nt++)
#pragma unroll
            for (int v = 0; v < 4; v++) { sa[nt][v] = 0.f; sbv[nt][v] = 0.f; sc[nt][v] = 0.f; }
        {
            int arow = mw * 16 + (lane & 15);
            int brow = nw2 * 16 + (lane & 7) + ((lane >> 4) & 1) * 8;
            uint32_t abase = sb + FQ_H + arow * F_ROWB;
            uint32_t bbase = kb + brow * F_ROWB;
            int aswz = arow & 7, bswz = brow & 7;
#pragma unroll
            for (int ks = 0; ks < 18; ks++) {
                int g = kh * 36 + 2 * ks;
                uint32_t qh4[4], ql4[4], bH[4], bL[4];
                uint32_t aaddr = abase + (((g + (lane >> 4)) ^ aswz) << 4);
                LDSM4(qh4, aaddr);
                LDSM4(ql4, aaddr + 36864);
                uint32_t baddr = bbase + (((g + ((lane >> 3) & 1)) ^ bswz) << 4);
                LDSM4(bH, baddr);
                LDSM4(bL, baddr + 36864);
#pragma unroll
                for (int nt = 0; nt < 2; nt++) {
                    MMA16816(sa[nt],  qh4, bH[nt * 2], bH[nt * 2 + 1]);
                    MMA16816(sbv[nt], qh4, bL[nt * 2], bL[nt * 2 + 1]);
                    MMA16816(sc[nt],  ql4, bH[nt * 2], bH[nt * 2 + 1]);
                }
            }
        }
        {
            float* Sp = (float*)(sm + FSP0 + kh * 4224);
            int r0 = mw * 16 + (lane >> 2);
            int c0 = nw2 * 16 + (lane & 3) * 2;
#pragma unroll
            for (int nt = 0; nt < 2; nt++) {
                int cc = c0 + nt * 8;
                Sp[r0 * 33 + cc]           = sa[nt][0] + sbv[nt][0] + sc[nt][0];
                Sp[r0 * 33 + cc + 1]       = sa[nt][1] + sbv[nt][1] + sc[nt][1];
                Sp[(r0 + 8) * 33 + cc]     = sa[nt][2] + sbv[nt][2] + sc[nt][2];
                Sp[(r0 + 8) * 33 + cc + 1] = sa[nt][3] + sbv[nt][3] + sc[nt][3];
            }
        }
        __syncthreads();

        {
            int row = tid >> 3, j = tid & 7;
            const float* sp0 = (const float*)(sm + FSP0) + row * 33 + j * 4;
            const float* sp1 = (const float*)(sm + FSP1) + row * 33 + j * 4;
            float s0 = sp0[0] + sp1[0];
            float s1 = sp0[1] + sp1[1];
            float s2 = sp0[2] + sp1[2];
            float s3 = sp0[3] + sp1[3];
            int kt0 = kt * 32, qrow = q0 + row, c0 = j * 4;
            if (kt0 + c0     > qrow) s0 = -1e30f;
            if (kt0 + c0 + 1 > qrow) s1 = -1e30f;
            if (kt0 + c0 + 2 > qrow) s2 = -1e30f;
            if (kt0 + c0 + 3 > qrow) s3 = -1e30f;
            float mloc = fmaxf(fmaxf(s0, s1), fmaxf(s2, s3));
#pragma unroll
            for (int o = 1; o < 8; o <<= 1) mloc = fmaxf(mloc, __shfl_xor_sync(0xffffffffu, mloc, o));
            float m_old = m_s[row];
            float mnew = fmaxf(m_old, mloc);
            float alpha = __expf(m_old - mnew);
            float p0 = __expf(s0 - mnew), p1 = __expf(s1 - mnew);
            float p2 = __expf(s2 - mnew), p3 = __expf(s3 - mnew);
            float lsum = p0 + p1 + p2 + p3;
#pragma unroll
            for (int o = 1; o < 8; o <<= 1) lsum += __shfl_xor_sync(0xffffffffu, lsum, o);

            __syncthreads();   // all Spart reads done before P overwrite

            __half* Ph = (__half*)(sm + FPH) + row * 40 + j * 4;
            __half* Pl = (__half*)(sm + FPL) + row * 40 + j * 4;
            __half h0 = __float2half_rn(p0), h1 = __float2half_rn(p1);
            __half h2 = __float2half_rn(p2), h3 = __float2half_rn(p3);
            Ph[0] = h0; Ph[1] = h1; Ph[2] = h2; Ph[3] = h3;
            Pl[0] = __float2half_rn(p0 - __half2float(h0));
            Pl[1] = __float2half_rn(p1 - __half2float(h1));
            Pl[2] = __float2half_rn(p2 - __half2float(h2));
            Pl[3] = __float2half_rn(p3 - __half2float(h3));
            if (j == 0) { m_s[row] = mnew; l_s[row] = l_s[row] * alpha + lsum; a_s[row] = alpha; }
        }
        __syncthreads();

        // ---- rescale O, then PV (2-term: P hi/lo x V hi) ----
        {
#pragma unroll
            for (int mt = 0; mt < 2; mt++) {
                int r = mt * 16 + (lane >> 2);
                float a0 = a_s[r], a1 = a_s[r + 8];
#pragma unroll
                for (int g8 = 0; g8 < 8; g8++) {
                    oacc[mt][g8][0] *= a0; oacc[mt][g8][1] *= a0;
                    oacc[mt][g8][2] *= a1; oacc[mt][g8][3] *= a1;
                }
            }
#pragma unroll
            for (int kk = 0; kk < 2; kk++) {
                uint32_t ph4[2][4], pl4[2][4];
#pragma unroll
                for (int mt = 0; mt < 2; mt++) {
                    int prow = mt * 16 + (lane & 15);
                    uint32_t paddr = sb + FPH + prow * 80 + (kk * 16 + (lane >> 4) * 8) * 2;
                    LDSM4(ph4[mt], paddr);
                    LDSM4(pl4[mt], paddr + (FPL - FPH));
                }
                int vrow = kk * 16 + (lane & 7) + ((lane >> 3) & 1) * 8;
                uint32_t vbase = kb + vrow * F_ROWB;
                int vswz = vrow & 7;
#pragma unroll
                for (int u = 0; u < 4; u++) {
                    int gp = wid * 8 + 2 * u + (lane >> 4);
                    uint32_t vaddr = vbase + ((gp ^ vswz) << 4);
                    uint32_t vh4[4];
                    LDSM4T(vh4, vaddr);
#pragma unroll
                    for (int mt = 0; mt < 2; mt++) {
                        MMA16816(oacc[mt][2*u],   ph4[mt], vh4[0], vh4[1]);
                        MMA16816(oacc[mt][2*u+1], ph4[mt], vh4[2], vh4[3]);
                        MMA16816(oacc[mt][2*u],   pl4[mt], vh4[0], vh4[1]);
                        MMA16816(oacc[mt][2*u+1], pl4[mt], vh4[2], vh4[3]);
                    }
                }
            }
        }
        __syncthreads();
    }

    // ---- write O as fp16 hi/lo ----
#pragma unroll
    for (int mt = 0; mt < 2; mt++) {
        int r = mt * 16 + (lane >> 2);
        float inv0 = 1.f / l_s[r];
        float inv1 = 1.f / l_s[r + 8];
        size_t t0 = (size_t)bb * SEQ + q0 + r;
        size_t off0 = t0 * (NH * KVL) + (size_t)h * KVL;
        size_t off1 = off0 + (size_t)8 * (NH * KVL);
#pragma unroll
        for (int g8 = 0; g8 < 8; g8++) {
            int col = wid * 64 + g8 * 8 + (lane & 3) * 2;
            __half2 lo0, lo1;
            __half2 hi0 = splith2(oacc[mt][g8][0] * inv0, oacc[mt][g8][1] * inv0, lo0);
            __half2 hi1 = splith2(oacc[mt][g8][2] * inv1, oacc[mt][g8][3] * inv1, lo1);
            *(__half2*)(Oh + off0 + col) = hi0;
            *(__half2*)(Ol + off0 + col) = lo0;
            *(__half2*)(Oh + off1 + col) = hi1;
            *(__half2*)(Ol + off1 + col) = lo1;
        }
    }
}

// ---------------- conversions / small kernels ----------------
__global__ void conv_hl4(const float4* __restrict__ in, __half2* __restrict__ hi,
                         __half2* __restrict__ lo, size_t n4)
{
    for (size_t i = (size_t)blockIdx.x * blockDim.x + threadIdx.x; i < n4;
         i += (size_t)gridDim.x * blockDim.x) {
        float4 v = in[i];
        __half2 l01, l23;
        __half2 h01 = splith2(v.x, v.y, l01);
        __half2 h23 = splith2(v.z, v.w, l23);
        hi[2 * i] = h01; hi[2 * i + 1] = h23;
        lo[2 * i] = l01; lo[2 * i + 1] = l23;
    }
}

// single fp16 (weights)
__global__ void conv_h4(const float4* __restrict__ in, __half2* __restrict__ out, size_t n4)
{
    for (size_t i = (size_t)blockIdx.x * blockDim.x + threadIdx.x; i < n4;
         i += (size_t)gridDim.x * blockDim.x) {
        float4 v = in[i];
        out[2 * i]     = __floats2half2_rn(v.x, v.y);
        out[2 * i + 1] = __floats2half2_rn(v.z, v.w);
    }
}

__global__ void conv_wkvbt(const float* __restrict__ w, __half* __restrict__ out)
{
    int idx = blockIdx.x * blockDim.x + threadIdx.x;
    const int total = NH * KVL * NOPE;
    if (idx >= total) return;
    int d = idx & (NOPE - 1);
    int c = (idx >> 7) & (KVL - 1);
    int h = idx >> 16;
    out[idx] = __float2half_rn(w[(size_t)(h * (NOPE + VH) + d) * KVL + c]);
}

__global__ __launch_bounds__(256)
void rmsnorm_hl(const float* __restrict__ in, int ldin,
                const float* __restrict__ w,
                __half* __restrict__ hi, __half* __restrict__ lo,
                int ldout, int width)
{
    const int row = blockIdx.x;
    const float* r = in + (size_t)row * ldin;
    const int tid = threadIdx.x;
    float ss = 0.f;
    for (int c = tid; c < width; c += 256) { float v = r[c]; ss += v * v; }
#pragma unroll
    for (int o = 16; o > 0; o >>= 1) ss += __shfl_xor_sync(0xffffffffu, ss, o);
    __shared__ float red[8];
    __shared__ float s_scale;
    if ((tid & 31) == 0) red[tid >> 5] = ss;
    __syncthreads();
    if (tid == 0) {
        float tot = 0.f;
#pragma unroll
        for (int i = 0; i < 8; i++) tot += red[i];
        s_scale = rsqrtf(tot / (float)width + EPS_F);
    }
    __syncthreads();
    float sc = s_scale;
    for (int c = tid * 2; c < width; c += 512) {
        float v0 = r[c] * sc * w[c];
        float v1 = r[c + 1] * sc * w[c + 1];
        __half2 l2;
        __half2 h2 = splith2(v0, v1, l2);
        *(__half2*)(hi + (size_t)row * ldout + c) = h2;
        *(__half2*)(lo + (size_t)row * ldout + c) = l2;
    }
}

__global__ void rope_fused(const float* __restrict__ q, const float* __restrict__ kv,
                           __half* __restrict__ qfh, __half* __restrict__ qfl,
                           __half* __restrict__ kfh, __half* __restrict__ kfl,
                           const float* __restrict__ fc, const float* __restrict__ fs)
{
    int idx = blockIdx.x * blockDim.x + threadIdx.x;
    const int total = TOK * 17 * 32;
    if (idx >= total) return;
    int i  = idx & 31;
    int hh = (idx >> 5) % 17;
    int t  = idx / (17 * 32);
    int s  = t & (SEQ - 1);
    float c  = fc[s * 32 + i];
    float sn = fs[s * 32 + i];
    if (hh < 16) {
        const float* p = q + (size_t)t * (NH * QKH) + hh * QKH + NOPE + 2 * i;
        float x0 = p[0], x1 = p[1];
        float re = (x0 * c - x1 * sn) * SCALE_F;
        float im = (x0 * sn + x1 * c) * SCALE_F;
        size_t o = (size_t)t * (NH * KD) + (size_t)hh * KD + KVL + 2 * i;
        __half2 l2;
        __half2 h2 = splith2(re, im, l2);
        *(__half2*)(qfh + o) = h2;
        *(__half2*)(qfl + o) = l2;
    } else {
        const float* p = kv + (size_t)t * KD + KVL + 2 * i;
        float x0 = p[0], x1 = p[1];
        float re = x0 * c - x1 * sn;
        float im = x0 * sn + x1 * c;
        size_t o = (size_t)t * KD + KVL + 2 * i;
        __half2 l2;
        __half2 h2 = splith2(re, im, l2);
        *(__half2*)(kfh + o) = h2;
        *(__half2*)(kfl + o) = l2;
    }
}

// ---------------- host launcher ----------------
extern "C" void kernel_launch(void* const* d_in, const int* in_sizes, int n_in,
                              void* d_out, int out_size)
{
    const float* x     = (const float*)d_in[0];
    const float* fcos  = (const float*)d_in[1];
    const float* fsin  = (const float*)d_in[2];
    const float* wq_a  = (const float*)d_in[4];
    const float* qnw   = (const float*)d_in[5];
    const float* wq_b  = (const float*)d_in[6];
    const float* wkv_a = (const float*)d_in[7];
    const float* kvnw  = (const float*)d_in[8];
    const float* wkv_b = (const float*)d_in[9];
    const float* wo    = (const float*)d_in[10];
    float* out = (float*)d_out;

    float *p_qa, *p_q, *p_kv;
    cudaGetSymbolAddress((void**)&p_qa, g_qa);
    cudaGetSymbolAddress((void**)&p_q,  g_q);
    cudaGetSymbolAddress((void**)&p_kv, g_kv);

    __half *xh,*xl,*qah,*qal,*qh,*ql,*oah,*oal,*o2h,*o2l;
    __half *wqa16,*wqb16,*wkva16,*wkvb16,*wkvbt16,*wo16;
    __half *qfh,*qfl,*kfh,*kfl;
    cudaGetSymbolAddress((void**)&xh, g_xh);     cudaGetSymbolAddress((void**)&xl, g_xl);
    cudaGetSymbolAddress((void**)&qah, g_qah);   cudaGetSymbolAddress((void**)&qal, g_qal);
    cudaGetSymbolAddress((void**)&qh, g_qh);     cudaGetSymbolAddress((void**)&ql, g_ql);
    cudaGetSymbolAddress((void**)&oah, g_oah);   cudaGetSymbolAddress((void**)&oal, g_oal);
    cudaGetSymbolAddress((void**)&o2h, g_o2h);   cudaGetSymbolAddress((void**)&o2l, g_o2l);
    cudaGetSymbolAddress((void**)&wqa16, g_wqa16);
    cudaGetSymbolAddress((void**)&wqb16, g_wqb16);
    cudaGetSymbolAddress((void**)&wkva16, g_wkva16);
    cudaGetSymbolAddress((void**)&wkvb16, g_wkvb16);
    cudaGetSymbolAddress((void**)&wkvbt16, g_wkvbt16);
    cudaGetSymbolAddress((void**)&wo16, g_wo16);
    cudaGetSymbolAddress((void**)&qfh, g_qfh);   cudaGetSymbolAddress((void**)&qfl, g_qfl);
    cudaGetSymbolAddress((void**)&kfh, g_kfh);   cudaGetSymbolAddress((void**)&kfl, g_kfl);

    cudaFuncSetAttribute(gemm_mma<0>, cudaFuncAttributeMaxDynamicSharedMemorySize, GSM_TOTAL);
    cudaFuncSetAttribute(gemm_mma<2>, cudaFuncAttributeMaxDynamicSharedMemorySize, GSM_TOTAL);
    cudaFuncSetAttribute(gemm_mma<3>, cudaFuncAttributeMaxDynamicSharedMemorySize, GSM_TOTAL);
    cudaFuncSetAttribute(flash_mma,   cudaFuncAttributeMaxDynamicSharedMemorySize, FLASH_SMEM);

    const int CT = 256;
    conv_hl4<<<1024, CT>>>((const float4*)x,     (__half2*)xh, (__half2*)xl, (size_t)TOK * DIM / 4);
    conv_h4<<<1024, CT>>>((const float4*)wq_a,  (__half2*)wqa16,  (size_t)QL * DIM / 4);
    conv_h4<<<1024, CT>>>((const float4*)wkv_a, (__half2*)wkva16, (size_t)KD * DIM / 4);
    conv_h4<<<1024, CT>>>((const float4*)wq_b,  (__half2*)wqb16,  (size_t)NH * QKH * QL / 4);
    conv_h4<<<1024, CT>>>((const float4*)wkv_b, (__half2*)wkvb16, (size_t)NH * (NOPE + VH) * KVL / 4);

    // 1) q_lora = x @ wq_a^T
    gemm_mma<0><<<dim3(QL / 128, TOK / 128, 1), 256, GSM_TOTAL>>>(
        xh, xl, DIM, 0, wqa16, DIM, 0, QL,
        p_qa, QL, 0, nullptr, nullptr, 0, 0, 1.f, DIM);

    conv_h4<<<1024, CT>>>((const float4*)wo, (__half2*)wo16, (size_t)DIM * NH * VH / 4);
    conv_wkvbt<<<(NH * KVL * NOPE + CT - 1) / CT, CT>>>(wkv_b, wkvbt16);

    // 2) kv = x @ wkv_a^T
    gemm_mma<0><<<dim3((KD + 127) / 128, TOK / 128, 1), 256, GSM_TOTAL>>>(
        xh, xl, DIM, 0, wkva16, DIM, 0, KD,
        p_kv, KD, 0, nullptr, nullptr, 0, 0, 1.f, DIM);
    // 3) rmsnorm q_lora -> hi/lo
    rmsnorm_hl<<<TOK, 256>>>(p_qa, QL, qnw, qah, qal, QL, QL);
    // 4) rmsnorm kv -> flash K layout cols 0..511 (hi/lo)
    rmsnorm_hl<<<TOK, 256>>>(p_kv, KD, kvnw, kfh, kfl, KD, KVL);
    // 5) q = q_lora_n @ wq_b^T
    gemm_mma<3><<<dim3((NH * QKH) / 128, TOK / 128, 1), 256, GSM_TOTAL>>>(
        qah, qal, QL, 0, wqb16, QL, 0, NH * QKH,
        p_q, NH * QKH, 0, qh, ql, NH * QKH, 0, 1.f, QL);
    // 6) rope -> flash layouts cols 512..575
    {
        int total = TOK * 17 * 32;
        rope_fused<<<(total + 255) / 256, 256>>>(p_q, p_kv, qfh, qfl, kfh, kfl, fcos, fsin);
    }
    // 7) q_abs -> scaled hi/lo into flash Q layout cols 0..511
    gemm_mma<2><<<dim3(KVL / 128, TOK / 128, NH), 256, GSM_TOTAL>>>(
        qh, ql, NH * QKH, QKH,
        wkvbt16, NOPE, (long long)KVL * NOPE, KVL,
        nullptr, 0, 0, qfh, qfl, NH * KD, KD, SCALE_F, NOPE);
    // 8) flash attention
    flash_mma<<<dim3(SEQ / 32, NH, NBATCH), 256, FLASH_SMEM>>>(qfh, qfl, kfh, kfl, oah, oal);
    // 9) o2 = o @ wkvb_v^T
    gemm_mma<2><<<dim3(VH / 128, TOK / 128, NH), 256, GSM_TOTAL>>>(
        oah, oal, NH * KVL, KVL,
        wkvb16 + (size_t)NOPE * KVL, KVL, (long long)(NOPE + VH) * KVL, VH,
        nullptr, 0, 0, o2h, o2l, NH * VH, VH, 1.f, KVL);
    // 10) out = o2 @ wo^T
    gemm_mma<0><<<dim3(DIM / 128, TOK / 128, 1), 256, GSM_TOTAL>>>(
        o2h, o2l, NH * VH, 0, wo16, NH * VH, 0, DIM,
        out, DIM, 0, nullptr, nullptr, 0, 0, 1.f, NH * VH);

    (void)in_sizes; (void)n_in; (void)out_size;
}

// round 14
// speedup vs baseline: 1.3353x; 1.3353x over previous
#include <cuda_runtime.h>
#include <cuda_bf16.h>
#include <math.h>
#include <stdint.h>

// ---------------- problem constants ----------------
#define SEQ    2048
#define NBATCH 2
#define TOK    (SEQ*NBATCH)
#define DIM    2048
#define QL     1536
#define KVL    512
#define NH     16
#define NOPE   128
#define ROPE_D 64
#define QKH    (NOPE+ROPE_D)
#define VH     128
#define KD     (KVL+ROPE_D)       // 576
#define SCALE_F 0.07216878364870322f
#define EPS_F  1e-6f

// ---------------- fp32 scratch ----------------
static __device__ __align__(16) float g_qa  [(size_t)TOK*QL];
static __device__ __align__(16) float g_kv  [(size_t)TOK*KD];

// ---------------- bf16 hi/lo scratch ----------------
static __device__ __align__(16) __nv_bfloat16 g_xh  [(size_t)TOK*DIM];
static __device__ __align__(16) __nv_bfloat16 g_xl  [(size_t)TOK*DIM];
static __device__ __align__(16) __nv_bfloat16 g_qah [(size_t)TOK*QL];
static __device__ __align__(16) __nv_bfloat16 g_qal [(size_t)TOK*QL];
static __device__ __align__(16) __nv_bfloat16 g_qh  [(size_t)TOK*NH*QKH];
static __device__ __align__(16) __nv_bfloat16 g_ql  [(size_t)TOK*NH*QKH];
static __device__ __align__(16) __nv_bfloat16 g_oah [(size_t)TOK*NH*KVL];
static __device__ __align__(16) __nv_bfloat16 g_oal [(size_t)TOK*NH*KVL];
static __device__ __align__(16) __nv_bfloat16 g_o2h [(size_t)TOK*NH*VH];
static __device__ __align__(16) __nv_bfloat16 g_o2l [(size_t)TOK*NH*VH];
static __device__ __align__(16) __nv_bfloat16 g_wqah [(size_t)QL*DIM];
static __device__ __align__(16) __nv_bfloat16 g_wqal [(size_t)QL*DIM];
static __device__ __align__(16) __nv_bfloat16 g_wqbh [(size_t)NH*QKH*QL];
static __device__ __align__(16) __nv_bfloat16 g_wqbl [(size_t)NH*QKH*QL];
static __device__ __align__(16) __nv_bfloat16 g_wkvah[(size_t)KD*DIM];
static __device__ __align__(16) __nv_bfloat16 g_wkval[(size_t)KD*DIM];
static __device__ __align__(16) __nv_bfloat16 g_wkvbh[(size_t)NH*(NOPE+VH)*KVL];
static __device__ __align__(16) __nv_bfloat16 g_wkvbl[(size_t)NH*(NOPE+VH)*KVL];
static __device__ __align__(16) __nv_bfloat16 g_wkvbth[(size_t)NH*KVL*NOPE];
static __device__ __align__(16) __nv_bfloat16 g_wkvbtl[(size_t)NH*KVL*NOPE];
static __device__ __align__(16) __nv_bfloat16 g_woh  [(size_t)DIM*NH*VH];
static __device__ __align__(16) __nv_bfloat16 g_wol  [(size_t)DIM*NH*VH];
// flash-packed Q [t][h][576] and K [t][576], Q pre-scaled
static __device__ __align__(16) __nv_bfloat16 g_qfh [(size_t)TOK*NH*KD];
static __device__ __align__(16) __nv_bfloat16 g_qfl [(size_t)TOK*NH*KD];
static __device__ __align__(16) __nv_bfloat16 g_kfh [(size_t)TOK*KD];
static __device__ __align__(16) __nv_bfloat16 g_kfl [(size_t)TOK*KD];

// ======================= helpers =======================
__device__ __forceinline__ uint32_t smem_u32(const void* p) {
    uint32_t a;
    asm("{ .reg .u64 t; cvta.to.shared.u64 t, %1; cvt.u32.u64 %0, t; }" : "=r"(a) : "l"(p));
    return a;
}
__device__ __forceinline__ void cpa16(uint32_t dst, const void* src, bool ok) {
    int sz = ok ? 16 : 0;
    asm volatile("cp.async.cg.shared.global [%0], [%1], 16, %2;"
                 :: "r"(dst), "l"(src), "r"(sz) : "memory");
}
#define LDSM4(r, addr) \
    asm volatile("ldmatrix.sync.aligned.m8n8.x4.shared.b16 {%0,%1,%2,%3}, [%4];" \
        : "=r"((r)[0]), "=r"((r)[1]), "=r"((r)[2]), "=r"((r)[3]) : "r"(addr))
#define LDSM4T(r, addr) \
    asm volatile("ldmatrix.sync.aligned.m8n8.x4.trans.shared.b16 {%0,%1,%2,%3}, [%4];" \
        : "=r"((r)[0]), "=r"((r)[1]), "=r"((r)[2]), "=r"((r)[3]) : "r"(addr))
#define MMA16816(d, a, b0, b1) \
    asm volatile("mma.sync.aligned.m16n8k16.row.col.f32.bf16.bf16.f32 " \
        "{%0,%1,%2,%3},{%4,%5,%6,%7},{%8,%9},{%0,%1,%2,%3};" \
        : "+f"((d)[0]), "+f"((d)[1]), "+f"((d)[2]), "+f"((d)[3]) \
        : "r"((a)[0]), "r"((a)[1]), "r"((a)[2]), "r"((a)[3]), "r"(b0), "r"(b1))

__device__ __forceinline__ __nv_bfloat162 split_hi2(float a, float b, __nv_bfloat162& lo) {
    __nv_bfloat162 hi;
    hi.x = __float2bfloat16(a); hi.y = __float2bfloat16(b);
    lo.x = __float2bfloat16(a - __bfloat162float(hi.x));
    lo.y = __float2bfloat16(b - __bfloat162float(hi.y));
    return hi;
}

// ======================= 3-stage mma.sync bf16x3 GEMM, 2 CTAs/SM (R11) =======================
#define GROW(row, g) ((uint32_t)((row) * 64 + ((((g) ^ ((row) >> 1)) & 3) << 4)))
#define T_A    0
#define T_AL   8192
#define T_BH   16384
#define T_BL   24576
#define STG_SZ 32768
#define GSTAGES 3
#define GSM_TOTAL (GSTAGES*STG_SZ)   // 98304 -> 2 CTAs/SM

template<int OMODE>   // 0 = fp32 C; 2 = bf16 hi/lo scaled; 3 = both
__global__ __launch_bounds__(256, 2)
void gemm_mma(const __nv_bfloat16* __restrict__ Ah, const __nv_bfloat16* __restrict__ Al,
              int lda, long long aoffz,
              const __nv_bfloat16* __restrict__ Bh, const __nv_bfloat16* __restrict__ Bl,
              int ldb, long long boffz, int Nmax,
              float* __restrict__ C, int ldc, long long coffz,
              __nv_bfloat16* __restrict__ Dh, __nv_bfloat16* __restrict__ Dl,
              int ldd, long long doffz, float cscale,
              int K)
{
    extern __shared__ __align__(128) char sm[];
    const int tid = threadIdx.x;
    const int wid = tid >> 5, lane = tid & 31;
    const long long z = blockIdx.z;
    Ah += z * aoffz; Al += z * aoffz;
    Bh += z * boffz; Bl += z * boffz;
    const int m0 = blockIdx.y * 128;
    const int n0 = blockIdx.x * 128;
    const uint32_t sbase = smem_u32(sm);
    const int nch = K >> 5;

    float acc[4][4][4];
#pragma unroll
    for (int i = 0; i < 4; i++)
#pragma unroll
        for (int j = 0; j < 4; j++)
#pragma unroll
            for (int v = 0; v < 4; v++) acc[i][j][v] = 0.f;

    auto issue = [&](int c) {
        const int s = c % GSTAGES;
        const int k0 = c << 5;
        const uint32_t sb = sbase + s * STG_SZ;
#pragma unroll
        for (int i = 0; i < 2; i++) {
            int g = tid + i * 256;
            int row = g >> 2, cg = g & 3;
            uint32_t so = GROW(row, cg);
            size_t ao = (size_t)(m0 + row) * lda + k0 + cg * 8;
            cpa16(sb + T_A  + so, Ah + ao, true);
            cpa16(sb + T_AL + so, Al + ao, true);
            int nr = n0 + row;
            bool ok = nr < Nmax;
            int nrc = ok ? nr : (Nmax - 1);
            size_t bo = (size_t)nrc * ldb + k0 + cg * 8;
            cpa16(sb + T_BH + so, Bh + bo, ok);
            cpa16(sb + T_BL + so, Bl + bo, ok);
        }
        asm volatile("cp.async.commit_group;" ::: "memory");
    };

#pragma unroll
    for (int i = 0; i < GSTAGES - 1; i++) if (i < nch) issue(i);

    const int my = wid >> 2;
    const int wx = wid & 3;

    for (int c = 0; c < nch; ++c) {
        int pend = nch - 1 - c;
        if (pend > GSTAGES - 2) pend = GSTAGES - 2;
        if (pend == 1) asm volatile("cp.async.wait_group 1;" ::: "memory");
        else           asm volatile("cp.async.wait_group 0;" ::: "memory");
        __syncthreads();
        if (c + GSTAGES - 1 < nch) issue(c + GSTAGES - 1);

        const uint32_t sb = sbase + (c % GSTAGES) * STG_SZ;
#pragma unroll
        for (int ks = 0; ks < 2; ks++) {
            const int kg = ks * 2;
            uint32_t bH[8], bL[8];
#pragma unroll
            for (int np = 0; np < 2; np++) {
                int row = wx * 32 + np * 16 + (lane & 7) + ((lane >> 4) & 1) * 8;
                int g = kg + ((lane >> 3) & 1);
                uint32_t bd = sb + GROW(row, g);
                LDSM4(&bH[np * 4], bd + T_BH);
                LDSM4(&bL[np * 4], bd + T_BL);
            }
#pragma unroll
            for (int mt = 0; mt < 4; mt++) {
                uint32_t aH[4], aL[4];
                int row = my * 64 + mt * 16 + (lane & 15);
                int g = kg + (lane >> 4);
                uint32_t ad = sb + GROW(row, g);
                LDSM4(aH, ad + T_A);
                LDSM4(aL, ad + T_AL);
#pragma unroll
                for (int nt = 0; nt < 4; nt++) {
                    MMA16816(acc[mt][nt], aH, bH[nt * 2], bH[nt * 2 + 1]);
                    MMA16816(acc[mt][nt], aH, bL[nt * 2], bL[nt * 2 + 1]);
                    MMA16816(acc[mt][nt], aL, bH[nt * 2], bH[nt * 2 + 1]);
                }
            }
        }
    }

    // ---- epilogue ----
#pragma unroll
    for (int mt = 0; mt < 4; mt++) {
        int row = m0 + my * 64 + mt * 16 + (lane >> 2);
#pragma unroll
        for (int nt = 0; nt < 4; nt++) {
            int col = n0 + wx * 32 + nt * 8 + (lane & 3) * 2;
            if (col < Nmax) {
                if (OMODE == 0 || OMODE == 3) {
                    float* cp = C + z * coffz;
                    *(float2*)(cp + (size_t)row * ldc + col) =
                        make_float2(acc[mt][nt][0], acc[mt][nt][1]);
                    *(float2*)(cp + (size_t)(row + 8) * ldc + col) =
                        make_float2(acc[mt][nt][2], acc[mt][nt][3]);
                }
                if (OMODE >= 2) {
                    __nv_bfloat16* dh = Dh + z * doffz;
                    __nv_bfloat16* dl = Dl + z * doffz;
                    __nv_bfloat162 lo0, lo1;
                    __nv_bfloat162 hi0 = split_hi2(acc[mt][nt][0] * cscale,
                                                   acc[mt][nt][1] * cscale, lo0);
                    __nv_bfloat162 hi1 = split_hi2(acc[mt][nt][2] * cscale,
                                                   acc[mt][nt][3] * cscale, lo1);
                    *(__nv_bfloat162*)(dh + (size_t)row * ldd + col)       = hi0;
                    *(__nv_bfloat162*)(dl + (size_t)row * ldd + col)       = lo0;
                    *(__nv_bfloat162*)(dh + (size_t)(row + 8) * ldd + col) = hi1;
                    *(__nv_bfloat162*)(dl + (size_t)(row + 8) * ldd + col) = lo1;
                }
            }
        }
    }
}

// ======================= flash attention, split-K QK (R8/R11 winner) =======================
#define F_ROWB 1152
#define FQ_H   0
#define FQ_L   36864
#define FK_BUF 73728
#define FTAIL  221184
#define FSP0   FTAIL
#define FSP1   (FTAIL+4224)
#define FST_M  (FTAIL+8448)
#define FST_L  (FTAIL+8576)
#define FST_A  (FTAIL+8704)
#define FPH    FTAIL
#define FPL    (FTAIL+2560)
#define FLASH_SMEM 230912

__global__ __launch_bounds__(256, 1)
void flash_mma(const __nv_bfloat16* __restrict__ Qh_g, const __nv_bfloat16* __restrict__ Ql_g,
               const __nv_bfloat16* __restrict__ Kh_g, const __nv_bfloat16* __restrict__ Kl_g,
               __nv_bfloat16* __restrict__ Oh, __nv_bfloat16* __restrict__ Ol)
{
    extern __shared__ __align__(128) char sm[];
    const int tid = threadIdx.x, lane = tid & 31, wid = tid >> 5;
    const int q0 = blockIdx.x * 32, h = blockIdx.y, bb = blockIdx.z;
    const uint32_t sb = smem_u32(sm);
    float* m_s = (float*)(sm + FST_M);
    float* l_s = (float*)(sm + FST_L);
    float* a_s = (float*)(sm + FST_A);

    {
        size_t qbase = ((size_t)(bb * SEQ + q0)) * (NH * KD) + (size_t)h * KD;
        for (int i = tid; i < 4608; i += 256) {
            int hl = (i >= 2304);
            int j = hl ? i - 2304 : i;
            int row = j / 72, g = j - row * 72;
            uint32_t dst = sb + (hl ? FQ_L : FQ_H) + row * F_ROWB + ((g ^ (row & 7)) << 4);
            const __nv_bfloat16* src = (hl ? Ql_g : Qh_g) + qbase + (size_t)row * (NH * KD) + g * 8;
            cpa16(dst, src, true);
        }
        asm volatile("cp.async.commit_group;" ::: "memory");
    }
    if (tid < 32) { m_s[tid] = -1e30f; l_s[tid] = 0.f; }

    auto load_k = [&](int kt, int s) {
        size_t kbase = ((size_t)bb * SEQ + kt * 32) * KD;
        uint32_t bufb = sb + FK_BUF + s * 73728;
        for (int i = tid; i < 4608; i += 256) {
            int hl = (i >= 2304);
            int j = hl ? i - 2304 : i;
            int row = j / 72, g = j - row * 72;
            uint32_t dst = bufb + hl * 36864 + row * F_ROWB + ((g ^ (row & 7)) << 4);
            const __nv_bfloat16* src = (hl ? Kl_g : Kh_g) + kbase + (size_t)row * KD + g * 8;
            cpa16(dst, src, true);
        }
        asm volatile("cp.async.commit_group;" ::: "memory");
    };

    load_k(0, 0);

    const int nkt = (q0 >> 5) + 1;

    const int mw  = wid & 1;
    const int nw2 = (wid >> 1) & 1;
    const int kh  = wid >> 2;

    float oacc[2][8][4];
#pragma unroll
    for (int a = 0; a < 2; a++)
#pragma unroll
        for (int b = 0; b < 8; b++)
#pragma unroll
            for (int v = 0; v < 4; v++) oacc[a][b][v] = 0.f;

    for (int kt = 0; kt < nkt; kt++) {
        if (kt + 1 < nkt) {
            load_k(kt + 1, (kt + 1) & 1);
            asm volatile("cp.async.wait_group 1;" ::: "memory");
        } else {
            asm volatile("cp.async.wait_group 0;" ::: "memory");
        }
        __syncthreads();
        const uint32_t kb = sb + FK_BUF + (kt & 1) * 73728;

        float sa[2][4], sbv[2][4], sc[2][4];
#pragma unroll
        for (int nt = 0; nt < 2; nt++)
#pragma unroll
            for (int v = 0; v < 4; v++) { sa[nt][v] = 0.f; sbv[nt][v] = 0.f; sc[nt][v] = 0.f; }
        {
            int arow = mw * 16 + (lane & 15);
            int brow = nw2 * 16 + (lane & 7) + ((lane >> 4) & 1) * 8;
            uint32_t abase = sb + FQ_H + arow * F_ROWB;
            uint32_t bbase = kb + brow * F_ROWB;
            int aswz = arow & 7, bswz = brow & 7;
#pragma unroll
            for (int ks = 0; ks < 18; ks++) {
                int g = kh * 36 + 2 * ks;
                uint32_t qh4[4], ql4[4], bH[4], bL[4];
                uint32_t aaddr = abase + (((g + (lane >> 4)) ^ aswz) << 4);
                LDSM4(qh4, aaddr);
                LDSM4(ql4, aaddr + 36864);
                uint32_t baddr = bbase + (((g + ((lane >> 3) & 1)) ^ bswz) << 4);
                LDSM4(bH, baddr);
                LDSM4(bL, baddr + 36864);
#pragma unroll
                for (int nt = 0; nt < 2; nt++) {
                    MMA16816(sa[nt],  qh4, bH[nt * 2], bH[nt * 2 + 1]);
                    MMA16816(sbv[nt], qh4, bL[nt * 2], bL[nt * 2 + 1]);
                    MMA16816(sc[nt],  ql4, bH[nt * 2], bH[nt * 2 + 1]);
                }
            }
        }
        {
            float* Sp = (float*)(sm + FSP0 + kh * 4224);
            int r0 = mw * 16 + (lane >> 2);
            int c0 = nw2 * 16 + (lane & 3) * 2;
#pragma unroll
            for (int nt = 0; nt < 2; nt++) {
                int cc = c0 + nt * 8;
                Sp[r0 * 33 + cc]           = sa[nt][0] + sbv[nt][0] + sc[nt][0];
                Sp[r0 * 33 + cc + 1]       = sa[nt][1] + sbv[nt][1] + sc[nt][1];
                Sp[(r0 + 8) * 33 + cc]     = sa[nt][2] + sbv[nt][2] + sc[nt][2];
                Sp[(r0 + 8) * 33 + cc + 1] = sa[nt][3] + sbv[nt][3] + sc[nt][3];
            }
        }
        __syncthreads();

        {
            int row = tid >> 3, j = tid & 7;
            const float* sp0 = (const float*)(sm + FSP0) + row * 33 + j * 4;
            const float* sp1 = (const float*)(sm + FSP1) + row * 33 + j * 4;
            float s0 = sp0[0] + sp1[0];
            float s1 = sp0[1] + sp1[1];
            float s2 = sp0[2] + sp1[2];
            float s3 = sp0[3] + sp1[3];
            int kt0 = kt * 32, qrow = q0 + row, c0 = j * 4;
            if (kt0 + c0     > qrow) s0 = -1e30f;
            if (kt0 + c0 + 1 > qrow) s1 = -1e30f;
            if (kt0 + c0 + 2 > qrow) s2 = -1e30f;
            if (kt0 + c0 + 3 > qrow) s3 = -1e30f;
            float mloc = fmaxf(fmaxf(s0, s1), fmaxf(s2, s3));
#pragma unroll
            for (int o = 1; o < 8; o <<= 1) mloc = fmaxf(mloc, __shfl_xor_sync(0xffffffffu, mloc, o));
            float m_old = m_s[row];
            float mnew = fmaxf(m_old, mloc);
            float alpha = __expf(m_old - mnew);
            float p0 = __expf(s0 - mnew), p1 = __expf(s1 - mnew);
            float p2 = __expf(s2 - mnew), p3 = __expf(s3 - mnew);
            float lsum = p0 + p1 + p2 + p3;
#pragma unroll
            for (int o = 1; o < 8; o <<= 1) lsum += __shfl_xor_sync(0xffffffffu, lsum, o);

            __syncthreads();

            __nv_bfloat16* Ph = (__nv_bfloat16*)(sm + FPH) + row * 40 + j * 4;
            __nv_bfloat16* Pl = (__nv_bfloat16*)(sm + FPL) + row * 40 + j * 4;
            __nv_bfloat16 h0 = __float2bfloat16(p0), h1 = __float2bfloat16(p1);
            __nv_bfloat16 h2 = __float2bfloat16(p2), h3 = __float2bfloat16(p3);
            Ph[0] = h0; Ph[1] = h1; Ph[2] = h2; Ph[3] = h3;
            Pl[0] = __float2bfloat16(p0 - __bfloat162float(h0));
            Pl[1] = __float2bfloat16(p1 - __bfloat162float(h1));
            Pl[2] = __float2bfloat16(p2 - __bfloat162float(h2));
            Pl[3] = __float2bfloat16(p3 - __bfloat162float(h3));
            if (j == 0) { m_s[row] = mnew; l_s[row] = l_s[row] * alpha + lsum; a_s[row] = alpha; }
        }
        __syncthreads();

        {
#pragma unroll
            for (int mt = 0; mt < 2; mt++) {
                int r = mt * 16 + (lane >> 2);
                float a0 = a_s[r], a1 = a_s[r + 8];
#pragma unroll
                for (int g8 = 0; g8 < 8; g8++) {
                    oacc[mt][g8][0] *= a0; oacc[mt][g8][1] *= a0;
                    oacc[mt][g8][2] *= a1; oacc[mt][g8][3] *= a1;
                }
            }
#pragma unroll
            for (int kk = 0; kk < 2; kk++) {
                uint32_t ph4[2][4], pl4[2][4];
#pragma unroll
                for (int mt = 0; mt < 2; mt++) {
                    int prow = mt * 16 + (lane & 15);
                    uint32_t paddr = sb + FPH + prow * 80 + (kk * 16 + (lane >> 4) * 8) * 2;
                    LDSM4(ph4[mt], paddr);
                    LDSM4(pl4[mt], paddr + (FPL - FPH));
                }
                int vrow = kk * 16 + (lane & 7) + ((lane >> 3) & 1) * 8;
                uint32_t vbase = kb + vrow * F_ROWB;
                int vswz = vrow & 7;
#pragma unroll
                for (int u = 0; u < 4; u++) {
                    int gp = wid * 8 + 2 * u + (lane >> 4);
                    uint32_t vaddr = vbase + ((gp ^ vswz) << 4);
                    uint32_t vh4[4], vl4[4];
                    LDSM4T(vh4, vaddr);
                    LDSM4T(vl4, vaddr + 36864);
#pragma unroll
                    for (int mt = 0; mt < 2; mt++) {
                        MMA16816(oacc[mt][2*u],   ph4[mt], vh4[0], vh4[1]);
                        MMA16816(oacc[mt][2*u+1], ph4[mt], vh4[2], vh4[3]);
                        MMA16816(oacc[mt][2*u],   pl4[mt], vh4[0], vh4[1]);
                        MMA16816(oacc[mt][2*u+1], pl4[mt], vh4[2], vh4[3]);
                        MMA16816(oacc[mt][2*u],   ph4[mt], vl4[0], vl4[1]);
                        MMA16816(oacc[mt][2*u+1], ph4[mt], vl4[2], vl4[3]);
                    }
                }
            }
        }
        __syncthreads();
    }

#pragma unroll
    for (int mt = 0; mt < 2; mt++) {
        int r = mt * 16 + (lane >> 2);
        float inv0 = 1.f / l_s[r];
        float inv1 = 1.f / l_s[r + 8];
        size_t t0 = (size_t)bb * SEQ + q0 + r;
        size_t off0 = t0 * (NH * KVL) + (size_t)h * KVL;
        size_t off1 = off0 + (size_t)8 * (NH * KVL);
#pragma unroll
        for (int g8 = 0; g8 < 8; g8++) {
            int col = wid * 64 + g8 * 8 + (lane & 3) * 2;
            __nv_bfloat162 lo0, lo1;
            __nv_bfloat162 hi0 = split_hi2(oacc[mt][g8][0] * inv0, oacc[mt][g8][1] * inv0, lo0);
            __nv_bfloat162 hi1 = split_hi2(oacc[mt][g8][2] * inv1, oacc[mt][g8][3] * inv1, lo1);
            *(__nv_bfloat162*)(Oh + off0 + col) = hi0;
            *(__nv_bfloat162*)(Ol + off0 + col) = lo0;
            *(__nv_bfloat162*)(Oh + off1 + col) = hi1;
            *(__nv_bfloat162*)(Ol + off1 + col) = lo1;
        }
    }
}

// ---------------- conversions / small kernels ----------------
__global__ void conv_hl4(const float4* __restrict__ in, __nv_bfloat162* __restrict__ hi,
                         __nv_bfloat162* __restrict__ lo, size_t n4)
{
    for (size_t i = (size_t)blockIdx.x * blockDim.x + threadIdx.x; i < n4;
         i += (size_t)gridDim.x * blockDim.x) {
        float4 v = in[i];
        __nv_bfloat162 l01, l23;
        __nv_bfloat162 h01 = split_hi2(v.x, v.y, l01);
        __nv_bfloat162 h23 = split_hi2(v.z, v.w, l23);
        hi[2 * i] = h01; hi[2 * i + 1] = h23;
        lo[2 * i] = l01; lo[2 * i + 1] = l23;
    }
}

__global__ void conv_wkvbt(const float* __restrict__ w, __nv_bfloat16* __restrict__ hi,
                           __nv_bfloat16* __restrict__ lo)
{
    int idx = blockIdx.x * blockDim.x + threadIdx.x;
    const int total = NH * KVL * NOPE;
    if (idx >= total) return;
    int d = idx & (NOPE - 1);
    int c = (idx >> 7) & (KVL - 1);
    int h = idx >> 16;
    float v = w[(size_t)(h * (NOPE + VH) + d) * KVL + c];
    __nv_bfloat16 hh = __float2bfloat16(v);
    hi[idx] = hh;
    lo[idx] = __float2bfloat16(v - __bfloat162float(hh));
}

__global__ __launch_bounds__(256)
void rmsnorm_hl(const float* __restrict__ in, int ldin,
                const float* __restrict__ w,
                __nv_bfloat16* __restrict__ hi, __nv_bfloat16* __restrict__ lo,
                int ldout, int width)
{
    const int row = blockIdx.x;
    const float* r = in + (size_t)row * ldin;
    const int tid = threadIdx.x;
    float ss = 0.f;
    for (int c = tid; c < width; c += 256) { float v = r[c]; ss += v * v; }
#pragma unroll
    for (int o = 16; o > 0; o >>= 1) ss += __shfl_xor_sync(0xffffffffu, ss, o);
    __shared__ float red[8];
    __shared__ float s_scale;
    if ((tid & 31) == 0) red[tid >> 5] = ss;
    __syncthreads();
    if (tid == 0) {
        float tot = 0.f;
#pragma unroll
        for (int i = 0; i < 8; i++) tot += red[i];
        s_scale = rsqrtf(tot / (float)width + EPS_F);
    }
    __syncthreads();
    float sc = s_scale;
    for (int c = tid * 2; c < width; c += 512) {
        float v0 = r[c] * sc * w[c];
        float v1 = r[c + 1] * sc * w[c + 1];
        __nv_bfloat162 l2;
        __nv_bfloat162 h2 = split_hi2(v0, v1, l2);
        *(__nv_bfloat162*)(hi + (size_t)row * ldout + c) = h2;
        *(__nv_bfloat162*)(lo + (size_t)row * ldout + c) = l2;
    }
}

// RoPE: q_pe reconstructed from bf16 hi/lo q (op5 output); k_pe from fp32 kv.
__global__ void rope_fused(const __nv_bfloat16* __restrict__ qh, const __nv_bfloat16* __restrict__ ql,
                           const float* __restrict__ kv,
                           __nv_bfloat16* __restrict__ qfh, __nv_bfloat16* __restrict__ qfl,
                           __nv_bfloat16* __restrict__ kfh, __nv_bfloat16* __restrict__ kfl,
                           const float* __restrict__ fc, const float* __restrict__ fs)
{
    int idx = blockIdx.x * blockDim.x + threadIdx.x;
    const int total = TOK * 17 * 32;
    if (idx >= total) return;
    int i  = idx & 31;
    int hh = (idx >> 5) % 17;
    int t  = idx / (17 * 32);
    int s  = t & (SEQ - 1);
    float c  = fc[s * 32 + i];
    float sn = fs[s * 32 + i];
    if (hh < 16) {
        size_t qo = (size_t)t * (NH * QKH) + hh * QKH + NOPE + 2 * i;
        float x0 = __bfloat162float(qh[qo])     + __bfloat162float(ql[qo]);
        float x1 = __bfloat162float(qh[qo + 1]) + __bfloat162float(ql[qo + 1]);
        float re = (x0 * c - x1 * sn) * SCALE_F;
        float im = (x0 * sn + x1 * c) * SCALE_F;
        size_t o = (size_t)t * (NH * KD) + (size_t)hh * KD + KVL + 2 * i;
        __nv_bfloat162 l2;
        __nv_bfloat162 h2 = split_hi2(re, im, l2);
        *(__nv_bfloat162*)(qfh + o) = h2;
        *(__nv_bfloat162*)(qfl + o) = l2;
    } else {
        const float* p = kv + (size_t)t * KD + KVL + 2 * i;
        float x0 = p[0], x1 = p[1];
        float re = x0 * c - x1 * sn;
        float im = x0 * sn + x1 * c;
        size_t o = (size_t)t * KD + KVL + 2 * i;
        __nv_bfloat162 l2;
        __nv_bfloat162 h2 = split_hi2(re, im, l2);
        *(__nv_bfloat162*)(kfh + o) = h2;
        *(__nv_bfloat162*)(kfl + o) = l2;
    }
}

// ---------------- host launcher ----------------
extern "C" void kernel_launch(void* const* d_in, const int* in_sizes, int n_in,
                              void* d_out, int out_size)
{
    const float* x     = (const float*)d_in[0];
    const float* fcos  = (const float*)d_in[1];
    const float* fsin  = (const float*)d_in[2];
    const float* wq_a  = (const float*)d_in[4];
    const float* qnw   = (const float*)d_in[5];
    const float* wq_b  = (const float*)d_in[6];
    const float* wkv_a = (const float*)d_in[7];
    const float* kvnw  = (const float*)d_in[8];
    const float* wkv_b = (const float*)d_in[9];
    const float* wo    = (const float*)d_in[10];
    float* out = (float*)d_out;

    float *p_qa, *p_kv;
    cudaGetSymbolAddress((void**)&p_qa, g_qa);
    cudaGetSymbolAddress((void**)&p_kv, g_kv);

    __nv_bfloat16 *xh,*xl,*qah,*qal,*qh,*ql,*oah,*oal,*o2h,*o2l;
    __nv_bfloat16 *wqah,*wqal,*wqbh,*wqbl,*wkvah,*wkval,*wkvbh,*wkvbl,*wkvbth,*wkvbtl,*woh,*wol;
    __nv_bfloat16 *qfh,*qfl,*kfh,*kfl;
    cudaGetSymbolAddress((void**)&xh, g_xh);     cudaGetSymbolAddress((void**)&xl, g_xl);
    cudaGetSymbolAddress((void**)&qah, g_qah);   cudaGetSymbolAddress((void**)&qal, g_qal);
    cudaGetSymbolAddress((void**)&qh, g_qh);     cudaGetSymbolAddress((void**)&ql, g_ql);
    cudaGetSymbolAddress((void**)&oah, g_oah);   cudaGetSymbolAddress((void**)&oal, g_oal);
    cudaGetSymbolAddress((void**)&o2h, g_o2h);   cudaGetSymbolAddress((void**)&o2l, g_o2l);
    cudaGetSymbolAddress((void**)&wqah, g_wqah); cudaGetSymbolAddress((void**)&wqal, g_wqal);
    cudaGetSymbolAddress((void**)&wqbh, g_wqbh); cudaGetSymbolAddress((void**)&wqbl, g_wqbl);
    cudaGetSymbolAddress((void**)&wkvah, g_wkvah); cudaGetSymbolAddress((void**)&wkval, g_wkval);
    cudaGetSymbolAddress((void**)&wkvbh, g_wkvbh); cudaGetSymbolAddress((void**)&wkvbl, g_wkvbl);
    cudaGetSymbolAddress((void**)&wkvbth, g_wkvbth); cudaGetSymbolAddress((void**)&wkvbtl, g_wkvbtl);
    cudaGetSymbolAddress((void**)&woh, g_woh);   cudaGetSymbolAddress((void**)&wol, g_wol);
    cudaGetSymbolAddress((void**)&qfh, g_qfh);   cudaGetSymbolAddress((void**)&qfl, g_qfl);
    cudaGetSymbolAddress((void**)&kfh, g_kfh);   cudaGetSymbolAddress((void**)&kfl, g_kfl);

    cudaFuncSetAttribute(gemm_mma<0>, cudaFuncAttributeMaxDynamicSharedMemorySize, GSM_TOTAL);
    cudaFuncSetAttribute(gemm_mma<2>, cudaFuncAttributeMaxDynamicSharedMemorySize, GSM_TOTAL);
    cudaFuncSetAttribute(gemm_mma<3>, cudaFuncAttributeMaxDynamicSharedMemorySize, GSM_TOTAL);
    cudaFuncSetAttribute(flash_mma,   cudaFuncAttributeMaxDynamicSharedMemorySize, FLASH_SMEM);

    const int CT = 256;
    conv_hl4<<<1024, CT>>>((const float4*)x,     (__nv_bfloat162*)xh,   (__nv_bfloat162*)xl,   (size_t)TOK * DIM / 4);
    conv_hl4<<<1024, CT>>>((const float4*)wq_a,  (__nv_bfloat162*)wqah, (__nv_bfloat162*)wqal, (size_t)QL * DIM / 4);
    conv_hl4<<<1024, CT>>>((const float4*)wkv_a, (__nv_bfloat162*)wkvah,(__nv_bfloat162*)wkval,(size_t)KD * DIM / 4);
    conv_hl4<<<1024, CT>>>((const float4*)wq_b,  (__nv_bfloat162*)wqbh, (__nv_bfloat162*)wqbl, (size_t)NH * QKH * QL / 4);
    conv_hl4<<<1024, CT>>>((const float4*)wkv_b, (__nv_bfloat162*)wkvbh,(__nv_bfloat162*)wkvbl,(size_t)NH * (NOPE + VH) * KVL / 4);

    // 1) q_lora = x @ wq_a^T
    gemm_mma<0><<<dim3(QL / 128, TOK / 128, 1), 256, GSM_TOTAL>>>(
        xh, xl, DIM, 0, wqah, wqal, DIM, 0, QL,
        p_qa, QL, 0, nullptr, nullptr, 0, 0, 1.f, DIM);

    conv_hl4<<<1024, CT>>>((const float4*)wo, (__nv_bfloat162*)woh, (__nv_bfloat162*)wol, (size_t)DIM * NH * VH / 4);
    conv_wkvbt<<<(NH * KVL * NOPE + CT - 1) / CT, CT>>>(wkv_b, wkvbth, wkvbtl);

    // 2) kv = x @ wkv_a^T
    gemm_mma<0><<<dim3((KD + 127) / 128, TOK / 128, 1), 256, GSM_TOTAL>>>(
        xh, xl, DIM, 0, wkvah, wkval, DIM, 0, KD,
        p_kv, KD, 0, nullptr, nullptr, 0, 0, 1.f, DIM);
    // 3) rmsnorm q_lora -> hi/lo
    rmsnorm_hl<<<TOK, 256>>>(p_qa, QL, qnw, qah, qal, QL, QL);
    // 4) rmsnorm kv -> flash K layout cols 0..511
    rmsnorm_hl<<<TOK, 256>>>(p_kv, KD, kvnw, kfh, kfl, KD, KVL);
    // 5) q = q_lora_n @ wq_b^T   (hi/lo only; no fp32 materialization)
    gemm_mma<2><<<dim3((NH * QKH) / 128, TOK / 128, 1), 256, GSM_TOTAL>>>(
        qah, qal, QL, 0, wqbh, wqbl, QL, 0, NH * QKH,
        nullptr, 0, 0, qh, ql, NH * QKH, 0, 1.f, QL);
    // 6) rope (reads q hi/lo) -> flash layouts cols 512..575
    {
        int total = TOK * 17 * 32;
        rope_fused<<<(total + 255) / 256, 256>>>(qh, ql, p_kv, qfh, qfl, kfh, kfl, fcos, fsin);
    }
    // 7) q_abs -> scaled hi/lo into flash Q layout cols 0..511
    gemm_mma<2><<<dim3(KVL / 128, TOK / 128, NH), 256, GSM_TOTAL>>>(
        qh, ql, NH * QKH, QKH,
        wkvbth, wkvbtl, NOPE, (long long)KVL * NOPE, KVL,
        nullptr, 0, 0, qfh, qfl, NH * KD, KD, SCALE_F, NOPE);
    // 8) flash attention
    flash_mma<<<dim3(SEQ / 32, NH, NBATCH), 256, FLASH_SMEM>>>(qfh, qfl, kfh, kfl, oah, oal);
    // 9) o2 = o @ wkvb_v^T
    gemm_mma<2><<<dim3(VH / 128, TOK / 128, NH), 256, GSM_TOTAL>>>(
        oah, oal, NH * KVL, KVL,
        wkvbh + (size_t)NOPE * KVL, wkvbl + (size_t)NOPE * KVL, KVL,
        (long long)(NOPE + VH) * KVL, VH,
        nullptr, 0, 0, o2h, o2l, NH * VH, VH, 1.f, KVL);
    // 10) out = o2 @ wo^T
    gemm_mma<0><<<dim3(DIM / 128, TOK / 128, 1), 256, GSM_TOTAL>>>(
        o2h, o2l, NH * VH, 0, woh, wol, NH * VH, 0, DIM,
        out, DIM, 0, nullptr, nullptr, 0, 0, 1.f, NH * VH);

    (void)in_sizes; (void)n_in; (void)out_size;
}